// round 16
// baseline (speedup 1.0000x reference)
#include <cuda_runtime.h>
#include <cuda_fp16.h>
#include <cstdint>

#define N_NODES 20000
#define N_EDGES 320000
#define C_DIM   256
#define H_HEADS 8
#define D_HEAD  32
#define L_LAYERS 5
#define T_DIM   64
#define MS_SLOTS 10
#define MD_DIM  128
#define NEG_SLOPE 0.2f
#define CAT_LD  (C_DIM + T_DIM)      // 320: [node | te]
#define KCAT    CAT_LD
#define NPB     4                    // nodes per edge_mem block (2 warps/node)

// ---------------- scratch buffers ---------------------------------------------
__device__ __half g_cat0[N_NODES * CAT_LD];
__device__ __half g_cat1[N_NODES * CAT_LD];
__device__ __half g_hbf [N_NODES * C_DIM];
__device__ __half g_xbf [N_NODES * 128];
__device__ float g_Wtg [L_LAYERS * T_DIM * C_DIM];
__device__ uint32_t g_Wipk[64 * C_DIM];
__device__ uint32_t g_Wcpk[L_LAYERS * (KCAT / 2) * C_DIM];
__device__ float g_es  [N_NODES * H_HEADS];
__device__ float g_ed  [N_NODES * H_HEADS];
__device__ float g_kall [L_LAYERS * MS_SLOTS * C_DIM];
__device__ float g_vall [L_LAYERS * MS_SLOTS * C_DIM];
__device__ float g_Ptall[L_LAYERS * MS_SLOTS * C_DIM];
__device__ float g_pool[C_DIM];
__device__ int   g_cnt   [N_NODES];
__device__ int   g_rowptr[N_NODES + 1];
__device__ int   g_cursor[N_NODES];
__device__ int   g_csrc  [N_EDGES];

// ---------------- Wtg = Wt @ Wg (fp32, small) ----------------------------------
__global__ void wtg_kernel(const float* __restrict__ Wt, const float* __restrict__ Wg,
                           float* __restrict__ Wtg) {
    __shared__ float swt[8][C_DIM];
    int l = blockIdx.x >> 3;
    int t0 = (blockIdx.x & 7) * 8;
    int c = threadIdx.x;
    const float* wt = Wt + (size_t)l * T_DIM * C_DIM;
    const float* wg = Wg + (size_t)l * C_DIM * C_DIM;
    for (int i = threadIdx.x; i < 8 * C_DIM; i += blockDim.x)
        (&swt[0][0])[i] = wt[(t0 + i / C_DIM) * C_DIM + (i % C_DIM)];
    __syncthreads();
    float acc[8];
#pragma unroll
    for (int j = 0; j < 8; j++) acc[j] = 0.f;
    for (int c2 = 0; c2 < C_DIM; c2++) {
        float wv = wg[c2 * C_DIM + c];
#pragma unroll
        for (int j = 0; j < 8; j++) acc[j] += swt[j][c2] * wv;
    }
#pragma unroll
    for (int j = 0; j < 8; j++)
        Wtg[(size_t)l * T_DIM * C_DIM + (t0 + j) * C_DIM + c] = acc[j];
}

// ---------------- fused prep (also zeroes pool) --------------------------------
#define CPX (N_NODES * 128)
#define CPT (N_NODES * T_DIM)
#define CWI (64 * C_DIM)
#define CWC (L_LAYERS * (KCAT / 2) * C_DIM)
#define PREP_TOTAL (CPX + CPT + CWI + CWC + C_DIM)

__device__ __forceinline__ uint32_t pack_h2(float w0, float w1) {
    __half2 p = __floats2half2_rn(w0, w1);
    return *reinterpret_cast<uint32_t*>(&p);
}

__global__ void prep_kernel(const float* __restrict__ x, const float* __restrict__ te,
                            const float* __restrict__ Wi, const float* __restrict__ Wg,
                            const float* __restrict__ Wtg,
                            __half* __restrict__ xbf,
                            __half* __restrict__ cat0, __half* __restrict__ cat1,
                            uint32_t* __restrict__ wipk, uint32_t* __restrict__ wcpk,
                            float* __restrict__ pool) {
    int i = blockIdx.x * blockDim.x + threadIdx.x;
    if (i < CPX) { xbf[i] = __float2half_rn(x[i]); return; }
    i -= CPX;
    if (i < CPT) {
        int n = i / T_DIM, t = i % T_DIM;
        __half v = __float2half_rn(te[i]);
        cat0[(size_t)n * CAT_LD + C_DIM + t] = v;
        cat1[(size_t)n * CAT_LD + C_DIM + t] = v;
        return;
    }
    i -= CPT;
    if (i < CWI) {
        int n = i % C_DIM, k2 = i / C_DIM;
        wipk[i] = pack_h2(Wi[(2 * k2) * C_DIM + n], Wi[(2 * k2 + 1) * C_DIM + n]);
        return;
    }
    i -= CWI;
    if (i < CWC) {
        int r = i % ((KCAT / 2) * C_DIM);
        int l = i / ((KCAT / 2) * C_DIM);
        int n = r % C_DIM, k2 = r / C_DIM;
        int k = 2 * k2;
        float w0, w1;
        if (k < C_DIM) {
            const float* w = Wg + (size_t)l * C_DIM * C_DIM;
            w0 = w[k * C_DIM + n];
            w1 = w[(k + 1) * C_DIM + n];
        } else {
            const float* w = Wtg + (size_t)l * T_DIM * C_DIM;
            w0 = w[(k - C_DIM) * C_DIM + n];
            w1 = w[(k + 1 - C_DIM) * C_DIM + n];
        }
        wcpk[i] = pack_h2(w0, w1);
        return;
    }
    i -= CWC;
    if (i < C_DIM) pool[i] = 0.f;
}

// ---------------- CSR build ---------------------------------------------------
__global__ void zero_int_kernel(int* p, int n) {
    int i = blockIdx.x * blockDim.x + threadIdx.x;
    if (i < n) p[i] = 0;
}
__global__ void count_kernel(const int* __restrict__ dst, int* __restrict__ cnt) {
    int e = blockIdx.x * blockDim.x + threadIdx.x;
    if (e < N_EDGES) atomicAdd(&cnt[dst[e]], 1);
}

__global__ void scan_kernel(const int* __restrict__ cnt,
                            int* __restrict__ rowptr, int* __restrict__ cursor) {
    const int PER = (N_NODES + 1023) / 1024;
    int tid = threadIdx.x;
    int s0 = tid * PER;
    int vals[PER];
    int local = 0;
#pragma unroll
    for (int k = 0; k < PER; k++) {
        int i = s0 + k;
        vals[k] = (i < N_NODES) ? cnt[i] : 0;
        local += vals[k];
    }
    int lane = tid & 31, w = tid >> 5;
    int x = local;
#pragma unroll
    for (int off = 1; off < 32; off <<= 1) {
        int t = __shfl_up_sync(0xFFFFFFFFu, x, off);
        if (lane >= off) x += t;
    }
    __shared__ int wsum[32];
    if (lane == 31) wsum[w] = x;
    __syncthreads();
    if (w == 0) {
        int y = wsum[lane];
#pragma unroll
        for (int off = 1; off < 32; off <<= 1) {
            int t = __shfl_up_sync(0xFFFFFFFFu, y, off);
            if (lane >= off) y += t;
        }
        wsum[lane] = y;
    }
    __syncthreads();
    int warpoff = (w > 0) ? wsum[w - 1] : 0;
    int excl = warpoff + x - local;
#pragma unroll
    for (int k = 0; k < PER; k++) {
        int i = s0 + k;
        if (i < N_NODES) { rowptr[i] = excl; cursor[i] = excl; }
        excl += vals[k];
    }
    if (tid == 1023) rowptr[N_NODES] = warpoff + x;
}

__global__ void scatter_kernel(const int* __restrict__ src, const int* __restrict__ dst,
                               int* __restrict__ cursor, int* __restrict__ csrc) {
    int e = blockIdx.x * blockDim.x + threadIdx.x;
    if (e < N_EDGES) {
        int pos = atomicAdd(&cursor[dst[e]], 1);
        csrc[pos] = src[e];
    }
}

// ---------------- k/v/Pt for all layers (two pipelined launches) ----------------
__global__ void kvall_kernel(const float* __restrict__ mem, const float* __restrict__ Wk,
                             const float* __restrict__ Wv,
                             float* __restrict__ kall, float* __restrict__ vall) {
    __shared__ float sm[MD_DIM];
    int l = blockIdx.x / MS_SLOTS;
    int m = blockIdx.x % MS_SLOTS;
    int c = threadIdx.x;
    for (int i = threadIdx.x; i < MD_DIM; i += blockDim.x) sm[i] = mem[m * MD_DIM + i];
    __syncthreads();
    const float* wk = Wk + (size_t)l * MD_DIM * C_DIM;
    const float* wv = Wv + (size_t)l * MD_DIM * C_DIM;
    float ak = 0.f, av = 0.f;
#pragma unroll 4
    for (int t = 0; t < MD_DIM; t++) {
        float mv = sm[t];
        ak += mv * wk[t * C_DIM + c];
        av += mv * wv[t * C_DIM + c];
    }
    kall[(size_t)blockIdx.x * C_DIM + c] = ak;
    vall[(size_t)blockIdx.x * C_DIM + c] = av;
}

__global__ void ptall_kernel(const float* __restrict__ Wq, const float* __restrict__ kall,
                             float* __restrict__ Ptall) {
    __shared__ float sk[C_DIM];
    int l = blockIdx.x / MS_SLOTS;
    int c = threadIdx.x;
    for (int i = threadIdx.x; i < C_DIM; i += blockDim.x)
        sk[i] = kall[(size_t)blockIdx.x * C_DIM + i];
    __syncthreads();
    const float* wq = Wq + (size_t)l * C_DIM * C_DIM + (size_t)c * C_DIM;
    float acc = 0.f;
#pragma unroll 4
    for (int c2 = 0; c2 < C_DIM; c2++) acc += wq[c2] * sk[c2];
    Ptall[(size_t)blockIdx.x * C_DIM + c] = acc;
}

// ---------------- FP16 tensor-core GEMM (m16n8k16), cp.async 3-stage ----------
#define TBM 160
#define TBN 128
#define TBK 32
#define NSTAGE 3
#define AS32 ((TBK / 2) + 4)
#define A_ST (TBM * AS32)
#define B_ST ((TBK / 2) * 136)
#define SMEM_U32 (NSTAGE * (A_ST + B_ST))

__device__ __forceinline__ void mma_f16(float* c, const uint32_t* a,
                                        uint32_t b0, uint32_t b1) {
    asm volatile(
        "mma.sync.aligned.m16n8k16.row.col.f32.f16.f16.f32 "
        "{%0,%1,%2,%3}, {%4,%5,%6,%7}, {%8,%9}, {%0,%1,%2,%3};\n"
        : "+f"(c[0]), "+f"(c[1]), "+f"(c[2]), "+f"(c[3])
        : "r"(a[0]), "r"(a[1]), "r"(a[2]), "r"(a[3]), "r"(b0), "r"(b1));
}

__device__ __forceinline__ void cp_async16(void* dst_smem, const void* src) {
    uint32_t d = (uint32_t)__cvta_generic_to_shared(dst_smem);
    asm volatile("cp.async.cg.shared.global [%0], [%1], 16;\n" :: "r"(d), "l"(src));
}
__device__ __forceinline__ void cp_commit() {
    asm volatile("cp.async.commit_group;\n");
}
template <int NN>
__device__ __forceinline__ void cp_wait() {
    asm volatile("cp.async.wait_group %0;\n" :: "n"(NN));
}

__global__ __launch_bounds__(256, 2)
void hgemm_kernel(const __half* __restrict__ A, int lda,
                  const uint32_t* __restrict__ Bpk,
                  const float* __restrict__ bias,
                  const float* __restrict__ Asv, const float* __restrict__ Adv,
                  float* __restrict__ es, float* __restrict__ ed,
                  __half* __restrict__ Cout, int out_ld,
                  int M, int Nn, int K, int epi) {
    extern __shared__ uint32_t smem[];
    uint32_t* As = smem;
    uint32_t* Bs = smem + NSTAGE * A_ST;

    int tid = threadIdx.x;
    int lane = tid & 31;
    int wid = tid >> 5;
    int wm = wid >> 2;
    int wn = wid & 3;
    int tg = lane & 3;
    int gid = lane >> 2;

    int bm = blockIdx.y * TBM;
    int bn = blockIdx.x * TBN;
    int nk = K / TBK;

    int b_r = tid >> 4;
    int b_c = (tid & 15) * 8;
    const __half* a_src_base = A + (size_t)(bm + tid) * lda;
    const uint32_t* b_src = Bpk + (size_t)b_r * Nn + bn + b_c;

#pragma unroll
    for (int s = 0; s < NSTAGE - 1; s++) {
        if (s < nk) {
            int k0 = s * TBK;
            if (tid < TBM) {
                uint32_t* ad = As + s * A_ST + tid * AS32;
                const __half* asrc = a_src_base + k0;
#pragma unroll
                for (int j = 0; j < 4; j++) cp_async16(ad + j * 4, asrc + j * 8);
            }
            uint32_t* bd = Bs + s * B_ST + b_r * 136 + b_c;
            size_t soff = (size_t)(k0 / 2) * Nn;
            cp_async16(bd, b_src + soff);
            cp_async16(bd + 4, b_src + soff + 4);
        }
        cp_commit();
    }

    float acc[5][4][4];
#pragma unroll
    for (int mt = 0; mt < 5; mt++)
#pragma unroll
        for (int nt = 0; nt < 4; nt++)
#pragma unroll
            for (int r = 0; r < 4; r++) acc[mt][nt][r] = 0.f;

    for (int kt = 0; kt < nk; kt++) {
        cp_wait<NSTAGE - 2>();
        __syncthreads();

        const uint32_t* as_ = As + (kt % NSTAGE) * A_ST;
        const uint32_t* bs_ = Bs + (kt % NSTAGE) * B_ST;

#pragma unroll
        for (int s = 0; s < 2; s++) {
            int k2q = s * 8;
            uint32_t af[5][4];
#pragma unroll
            for (int mt = 0; mt < 5; mt++) {
                int m0 = wm * 80 + mt * 16 + gid;
                af[mt][0] = as_[m0 * AS32 + k2q + tg];
                af[mt][1] = as_[(m0 + 8) * AS32 + k2q + tg];
                af[mt][2] = as_[m0 * AS32 + k2q + tg + 4];
                af[mt][3] = as_[(m0 + 8) * AS32 + k2q + tg + 4];
            }
#pragma unroll
            for (int nt = 0; nt < 4; nt++) {
                int n0 = wn * 32 + nt * 8 + gid;
                uint32_t b0 = bs_[(k2q + tg) * 136 + n0];
                uint32_t b1 = bs_[(k2q + tg + 4) * 136 + n0];
#pragma unroll
                for (int mt = 0; mt < 5; mt++)
                    mma_f16(acc[mt][nt], af[mt], b0, b1);
            }
        }

        int s2 = (kt + NSTAGE - 1) % NSTAGE;
        if (kt + NSTAGE - 1 < nk) {
            int k0 = (kt + NSTAGE - 1) * TBK;
            if (tid < TBM) {
                uint32_t* ad = As + s2 * A_ST + tid * AS32;
                const __half* asrc = a_src_base + k0;
#pragma unroll
                for (int j = 0; j < 4; j++) cp_async16(ad + j * 4, asrc + j * 8);
            }
            uint32_t* bd = Bs + s2 * B_ST + b_r * 136 + b_c;
            size_t soff = (size_t)(k0 / 2) * Nn;
            cp_async16(bd, b_src + soff);
            cp_async16(bd + 4, b_src + soff + 4);
        }
        cp_commit();
    }

    // ---- epilogue ----
    float as_c[8], ad_c[8];
    if (epi == 3) {
#pragma unroll
        for (int nt = 0; nt < 4; nt++) {
            int c = bn + wn * 32 + nt * 8 + tg * 2;
            as_c[nt * 2]     = Asv[c];
            as_c[nt * 2 + 1] = Asv[c + 1];
            ad_c[nt * 2]     = Adv[c];
            ad_c[nt * 2 + 1] = Adv[c + 1];
        }
    }
    int head = (bn >> 5) + wn;

#pragma unroll
    for (int mt = 0; mt < 5; mt++) {
#pragma unroll
        for (int half = 0; half < 2; half++) {
            int r = bm + wm * 80 + mt * 16 + gid + half * 8;
            float ps = 0.f, pd = 0.f;
#pragma unroll
            for (int nt = 0; nt < 4; nt++) {
                int c = bn + wn * 32 + nt * 8 + tg * 2;
                float v0 = acc[mt][nt][half * 2 + 0];
                float v1 = acc[mt][nt][half * 2 + 1];
                if (epi == 1) {
                    v0 = fmaxf(v0 + bias[c], 0.f);
                    v1 = fmaxf(v1 + bias[c + 1], 0.f);
                } else {
                    ps += v0 * as_c[nt * 2] + v1 * as_c[nt * 2 + 1];
                    pd += v0 * ad_c[nt * 2] + v1 * ad_c[nt * 2 + 1];
                }
                __half2 pv = __floats2half2_rn(v0, v1);
                *reinterpret_cast<__half2*>(&Cout[(size_t)r * out_ld + c]) = pv;
            }
            if (epi == 3) {
                ps += __shfl_xor_sync(0xFFFFFFFFu, ps, 1);
                ps += __shfl_xor_sync(0xFFFFFFFFu, ps, 2);
                pd += __shfl_xor_sync(0xFFFFFFFFu, pd, 1);
                pd += __shfl_xor_sync(0xFFFFFFFFu, pd, 2);
                if (tg == 0) {
                    es[r * H_HEADS + head] = ps;
                    ed[r * H_HEADS + head] = pd;
                }
            }
        }
    }
}

// ---------------- fused edge aggregation + memory cross-attention --------------
// 2 warps per node (NPB=4 nodes/block). Warp pair splits the edge list by
// alternating 32-edge chunks; partial acc/dsum combined via smem; even warp
// finishes softmax + memory attention + store (+ pool on last layer).
__global__ __launch_bounds__(256)
void edge_mem_kernel(const __half* __restrict__ h, const int* __restrict__ rowptr,
                     const int* __restrict__ csrc, const float* __restrict__ es,
                     const float* __restrict__ ed,
                     const float* __restrict__ Pt, const float* __restrict__ vb,
                     const __half* __restrict__ xin,
                     __half* __restrict__ node_out, float* __restrict__ pool_out) {
    __shared__ float sp[MS_SLOTS][C_DIM];
    __shared__ float sv[MS_SLOTS][C_DIM];
    __shared__ float sw[8][32][8];
    __shared__ int   ss[8][32];
    __shared__ float sacc[8][C_DIM];     // per-warp partial acc
    __shared__ float sds[8][8];          // per-warp per-head dsum
    __shared__ float spool[C_DIM];
    for (int i = threadIdx.x; i < MS_SLOTS * C_DIM; i += blockDim.x) {
        (&sp[0][0])[i] = Pt[i];
        (&sv[0][0])[i] = vb[i];
    }
    if (pool_out) spool[threadIdx.x] = 0.f;
    __syncthreads();

    int warp = threadIdx.x >> 5, lane = threadIdx.x & 31;
    int pair = warp >> 1;            // 0..3
    int sub  = warp & 1;             // 0 or 1
    int n = blockIdx.x * NPB + pair; // grid*NPB == N_NODES exactly
    int beg = rowptr[n], end = rowptr[n + 1];

    float edn[8];
#pragma unroll
    for (int j = 0; j < 8; j++) edn[j] = ed[n * 8 + j];

    int head = lane >> 2;
    float acc[8];
#pragma unroll
    for (int k = 0; k < 8; k++) acc[k] = 0.f;
    float dsum[8];
#pragma unroll
    for (int j = 0; j < 8; j++) dsum[j] = 0.f;

    // this warp takes chunks beg + (sub + 2t)*32
    for (int base = beg + sub * 32; base < end; base += 64) {
        int i = base + lane;
        int s = -1;
        float w[8];
        if (i < end) {
            s = csrc[i];
#pragma unroll
            for (int j = 0; j < 8; j++) {
                float lg = es[s * 8 + j] + edn[j];
                lg = (lg > 0.f) ? lg : NEG_SLOPE * lg;
                w[j] = __expf(lg);
                dsum[j] += w[j];
            }
        } else {
#pragma unroll
            for (int j = 0; j < 8; j++) w[j] = 0.f;
        }
        ss[warp][lane] = s;
#pragma unroll
        for (int j = 0; j < 8; j++) sw[warp][lane][j] = w[j];
        __syncwarp();
        int cnt = min(32, end - base);
        if (cnt > 0) {
            uint4 pf[4];
#pragma unroll
            for (int k = 0; k < 4; k++) {
                if (k < cnt)
                    pf[k] = *reinterpret_cast<const uint4*>(
                        &h[(size_t)ss[warp][k] * C_DIM + lane * 8]);
            }
            for (int e2 = 0; e2 < cnt; e2++) {
                uint4 cur = pf[e2 & 3];
                int nxt = e2 + 4;
                if (nxt < cnt) {
                    pf[e2 & 3] = *reinterpret_cast<const uint4*>(
                        &h[(size_t)ss[warp][nxt] * C_DIM + lane * 8]);
                }
                float we = sw[warp][e2][head];
                float2 f0 = __half22float2(*reinterpret_cast<__half2*>(&cur.x));
                float2 f1 = __half22float2(*reinterpret_cast<__half2*>(&cur.y));
                float2 f2 = __half22float2(*reinterpret_cast<__half2*>(&cur.z));
                float2 f3 = __half22float2(*reinterpret_cast<__half2*>(&cur.w));
                acc[0] += we * f0.x; acc[1] += we * f0.y;
                acc[2] += we * f1.x; acc[3] += we * f1.y;
                acc[4] += we * f2.x; acc[5] += we * f2.y;
                acc[6] += we * f3.x; acc[7] += we * f3.y;
            }
        }
        __syncwarp();
    }
    // in-warp dsum reduce (per head), publish partials
#pragma unroll
    for (int off = 16; off > 0; off >>= 1)
#pragma unroll
        for (int j = 0; j < 8; j++) dsum[j] += __shfl_xor_sync(0xFFFFFFFFu, dsum[j], off);
    if (lane < 8) sds[warp][lane] = dsum[lane];
#pragma unroll
    for (int j = 0; j < 8; j++) sacc[warp][lane * 8 + j] = acc[j];
    __syncthreads();

    if (sub == 0) {
        float accC[8];
#pragma unroll
        for (int j = 0; j < 8; j++)
            accC[j] = sacc[warp][lane * 8 + j] + sacc[warp + 1][lane * 8 + j];
        float dsh = sds[warp][head] + sds[warp + 1][head];

        float inv = 1.0f / (dsh + 1e-16f);
        float mid[8];
#pragma unroll
        for (int j = 0; j < 8; j++) mid[j] = fmaxf(accC[j] * inv, 0.f);

        float s[MS_SLOTS];
#pragma unroll
        for (int m = 0; m < MS_SLOTS; m++) {
            const float* pr = &sp[m][lane * 8];
            float p = mid[0] * pr[0] + mid[1] * pr[1] + mid[2] * pr[2] + mid[3] * pr[3]
                    + mid[4] * pr[4] + mid[5] * pr[5] + mid[6] * pr[6] + mid[7] * pr[7];
#pragma unroll
            for (int off = 16; off > 0; off >>= 1) p += __shfl_xor_sync(0xFFFFFFFFu, p, off);
            s[m] = p * 0.0625f;
        }
        float mx = s[0];
#pragma unroll
        for (int m = 1; m < MS_SLOTS; m++) mx = fmaxf(mx, s[m]);
        float sum = 0.f;
#pragma unroll
        for (int m = 0; m < MS_SLOTS; m++) { s[m] = __expf(s[m] - mx); sum += s[m]; }
        float invs = 1.0f / sum;

        uint4 xv = *reinterpret_cast<const uint4*>(&xin[(size_t)n * CAT_LD + lane * 8]);
        float2 x0 = __half22float2(*reinterpret_cast<__half2*>(&xv.x));
        float2 x1 = __half22float2(*reinterpret_cast<__half2*>(&xv.y));
        float2 x2 = __half22float2(*reinterpret_cast<__half2*>(&xv.z));
        float2 x3 = __half22float2(*reinterpret_cast<__half2*>(&xv.w));
        float o[8] = {mid[0] + x0.x, mid[1] + x0.y, mid[2] + x1.x, mid[3] + x1.y,
                      mid[4] + x2.x, mid[5] + x2.y, mid[6] + x3.x, mid[7] + x3.y};
#pragma unroll
        for (int m = 0; m < MS_SLOTS; m++) {
            float a = s[m] * invs;
            const float4* vp = reinterpret_cast<const float4*>(&sv[m][lane * 8]);
            float4 v0 = vp[0], v1 = vp[1];
            o[0] += a * v0.x; o[1] += a * v0.y; o[2] += a * v0.z; o[3] += a * v0.w;
            o[4] += a * v1.x; o[5] += a * v1.y; o[6] += a * v1.z; o[7] += a * v1.w;
        }
#pragma unroll
        for (int j = 0; j < 8; j++) o[j] = fmaxf(o[j], 0.f);
        __half2 b0 = __floats2half2_rn(o[0], o[1]);
        __half2 b1 = __floats2half2_rn(o[2], o[3]);
        __half2 b2 = __floats2half2_rn(o[4], o[5]);
        __half2 b3 = __floats2half2_rn(o[6], o[7]);
        uint4 pk;
        pk.x = *reinterpret_cast<uint32_t*>(&b0);
        pk.y = *reinterpret_cast<uint32_t*>(&b1);
        pk.z = *reinterpret_cast<uint32_t*>(&b2);
        pk.w = *reinterpret_cast<uint32_t*>(&b3);
        *reinterpret_cast<uint4*>(&node_out[(size_t)n * CAT_LD + lane * 8]) = pk;

        if (pool_out) {
#pragma unroll
            for (int j = 0; j < 8; j++) atomicAdd(&spool[lane * 8 + j], o[j]);
        }
    }

    if (pool_out) {
        __syncthreads();
        atomicAdd(&pool_out[threadIdx.x], spool[threadIdx.x]);
    }
}

// ---------------- final projection ---------------------------------------------
__global__ void final_kernel(const float* __restrict__ pool, const float* __restrict__ mem,
                             const float* __restrict__ Wc, const float* __restrict__ bc,
                             float* __restrict__ out) {
    __shared__ float s0[512], s1[512];
    int i = threadIdx.x;
    float val = 0.f;
    if (i < C_DIM) {
        val = pool[i] * (1.0f / (float)N_NODES);
    } else if (i < C_DIM + MD_DIM) {
        int t = i - C_DIM;
        float a = 0.f;
#pragma unroll
        for (int m = 0; m < MS_SLOTS; m++) a += mem[m * MD_DIM + t];
        val = a * (1.0f / (float)MS_SLOTS);
    }
    float c0 = 0.f, c1 = 0.f;
    if (i < C_DIM + MD_DIM) { c0 = val * Wc[i * 2 + 0]; c1 = val * Wc[i * 2 + 1]; }
    s0[i] = c0; s1[i] = c1;
    __syncthreads();
    for (int st = 256; st > 0; st >>= 1) {
        if (i < st) { s0[i] += s0[i + st]; s1[i] += s1[i + st]; }
        __syncthreads();
    }
    if (i == 0) { out[0] = s0[0] + bc[0]; out[1] = s1[0] + bc[1]; }
}

// ---------------- streams -----------------------------------------------------
struct StreamBundle {
    cudaStream_t s1 = nullptr, s2 = nullptr;
    cudaEvent_t evFork = nullptr, evS1 = nullptr, evS2 = nullptr;
    bool ok = false;
    StreamBundle() {
        ok = (cudaStreamCreateWithFlags(&s1, cudaStreamNonBlocking) == cudaSuccess) &&
             (cudaStreamCreateWithFlags(&s2, cudaStreamNonBlocking) == cudaSuccess) &&
             (cudaEventCreateWithFlags(&evFork, cudaEventDisableTiming) == cudaSuccess) &&
             (cudaEventCreateWithFlags(&evS1, cudaEventDisableTiming) == cudaSuccess) &&
             (cudaEventCreateWithFlags(&evS2, cudaEventDisableTiming) == cudaSuccess);
    }
};
static StreamBundle g_sb;

// ---------------- host launch -------------------------------------------------
static void* getsym(const void* symbol) {
    void* p = nullptr;
    cudaGetSymbolAddress(&p, symbol);
    return p;
}

extern "C" void kernel_launch(void* const* d_in, const int* in_sizes, int n_in,
                              void* d_out, int out_size) {
    const float* x    = (const float*)d_in[0];
    const int*   ei   = (const int*)  d_in[1];
    const float* te   = (const float*)d_in[2];
    const float* Wi   = (const float*)d_in[3];
    const float* bi   = (const float*)d_in[4];
    const float* Wg   = (const float*)d_in[5];
    const float* a_s  = (const float*)d_in[6];
    const float* a_d  = (const float*)d_in[7];
    const float* Wt   = (const float*)d_in[8];
    const float* Wq   = (const float*)d_in[9];
    const float* Wk   = (const float*)d_in[10];
    const float* Wv   = (const float*)d_in[11];
    const float* mem  = (const float*)d_in[12];
    const float* Wc   = (const float*)d_in[13];
    const float* bc   = (const float*)d_in[14];
    float* out = (float*)d_out;

    __half* cat0 = (__half*)getsym(g_cat0);
    __half* cat1 = (__half*)getsym(g_cat1);
    __half* hbf  = (__half*)getsym(g_hbf);
    __half* xbf  = (__half*)getsym(g_xbf);
    float* Wtg  = (float*)getsym(g_Wtg);
    uint32_t* Wipk = (uint32_t*)getsym(g_Wipk);
    uint32_t* Wcpk = (uint32_t*)getsym(g_Wcpk);
    float* esb   = (float*)getsym(g_es);
    float* edb   = (float*)getsym(g_ed);
    float* kall  = (float*)getsym(g_kall);
    float* vall  = (float*)getsym(g_vall);
    float* Ptall = (float*)getsym(g_Ptall);
    float* pool  = (float*)getsym(g_pool);
    int* cnt     = (int*)getsym(g_cnt);
    int* rowptr  = (int*)getsym(g_rowptr);
    int* cursor  = (int*)getsym(g_cursor);
    int* csrc    = (int*)getsym(g_csrc);

    const int* src = ei;
    const int* dst = ei + N_EDGES;

    const int smem_bytes = SMEM_U32 * 4;   // 64512
    static bool attr_set = false;
    if (!attr_set) {
        cudaFuncSetAttribute(hgemm_kernel, cudaFuncAttributeMaxDynamicSharedMemorySize,
                             smem_bytes);
        attr_set = true;
    }

    bool use_streams = g_sb.ok;
    cudaStream_t sc = use_streams ? g_sb.s1 : (cudaStream_t)0;
    cudaStream_t sk = use_streams ? g_sb.s2 : (cudaStream_t)0;

    if (use_streams) {
        cudaEventRecord(g_sb.evFork, 0);
        cudaStreamWaitEvent(g_sb.s1, g_sb.evFork, 0);
        cudaStreamWaitEvent(g_sb.s2, g_sb.evFork, 0);
    }

    // side stream 1: CSR build (hidden under main-stream prep + GEMMs)
    zero_int_kernel<<<(N_NODES + 255) / 256, 256, 0, sc>>>(cnt, N_NODES);
    count_kernel<<<(N_EDGES + 255) / 256, 256, 0, sc>>>(dst, cnt);
    scan_kernel<<<1, 1024, 0, sc>>>(cnt, rowptr, cursor);
    scatter_kernel<<<(N_EDGES + 255) / 256, 256, 0, sc>>>(src, dst, cursor, csrc);

    // side stream 2: k/v then Pt (two pipelined launches)
    kvall_kernel<<<L_LAYERS * MS_SLOTS, 256, 0, sk>>>(mem, Wk, Wv, kall, vall);
    ptall_kernel<<<L_LAYERS * MS_SLOTS, 256, 0, sk>>>(Wq, kall, Ptall);

    if (use_streams) {
        cudaEventRecord(g_sb.evS1, g_sb.s1);
        cudaEventRecord(g_sb.evS2, g_sb.s2);
    }

    // main stream: Wtg = Wt@Wg, then converts + packing (+pool zero)
    wtg_kernel<<<L_LAYERS * 8, 256>>>(Wt, Wg, Wtg);
    prep_kernel<<<(PREP_TOTAL + 255) / 256, 256>>>(x, te, Wi, Wg, Wtg, xbf, cat0, cat1,
                                                   Wipk, Wcpk, pool);

    // input projection: cat0[:,0:256] = relu(x @ Wi + bi)   (fp16, stride 320)
    dim3 gemm_grid(C_DIM / TBN, N_NODES / TBM);   // (2, 125)
    hgemm_kernel<<<gemm_grid, 256, smem_bytes>>>(xbf, 128, Wipk, bi,
                                                 nullptr, nullptr, nullptr, nullptr,
                                                 cat0, CAT_LD, N_NODES, C_DIM, 128, 1);

    if (use_streams) {
        cudaStreamWaitEvent(0, g_sb.evS1, 0);
        cudaStreamWaitEvent(0, g_sb.evS2, 0);
    }

    __half* cur = cat0;
    __half* nxt = cat1;
    for (int l = 0; l < L_LAYERS; l++) {
        hgemm_kernel<<<gemm_grid, 256, smem_bytes>>>(cur, CAT_LD,
                                                     Wcpk + (size_t)l * (KCAT / 2) * C_DIM,
                                                     nullptr,
                                                     a_s + l * H_HEADS * D_HEAD,
                                                     a_d + l * H_HEADS * D_HEAD, esb, edb,
                                                     hbf, C_DIM, N_NODES, C_DIM, KCAT, 3);
        float* pout = (l == L_LAYERS - 1) ? pool : nullptr;
        edge_mem_kernel<<<N_NODES / NPB, 256>>>(hbf, rowptr, csrc, esb, edb,
                                                Ptall + (size_t)l * MS_SLOTS * C_DIM,
                                                vall + (size_t)l * MS_SLOTS * C_DIM,
                                                cur, nxt, pout);
        __half* tmp = cur; cur = nxt; nxt = tmp;
    }

    final_kernel<<<1, 512>>>(pool, mem, Wc, bc, out);
}

// round 17
// speedup vs baseline: 1.2199x; 1.2199x over previous
#include <cuda_runtime.h>
#include <cuda_fp16.h>
#include <cstdint>

#define N_NODES 20000
#define N_EDGES 320000
#define C_DIM   256
#define H_HEADS 8
#define D_HEAD  32
#define L_LAYERS 5
#define T_DIM   64
#define MS_SLOTS 10
#define MD_DIM  128
#define NEG_SLOPE 0.2f
#define CAT_LD  (C_DIM + T_DIM)      // 320: [node | te]
#define KCAT    CAT_LD

// ---------------- scratch buffers ---------------------------------------------
__device__ __half g_cat0[N_NODES * CAT_LD];
__device__ __half g_cat1[N_NODES * CAT_LD];
__device__ __half g_hbf [N_NODES * C_DIM];
__device__ __half g_xbf [N_NODES * 128];
__device__ float g_Wtg [L_LAYERS * T_DIM * C_DIM];
__device__ uint32_t g_Wipk[64 * C_DIM];
__device__ uint32_t g_Wcpk[L_LAYERS * (KCAT / 2) * C_DIM];
__device__ float g_es  [N_NODES * H_HEADS];
__device__ float g_ed  [N_NODES * H_HEADS];
__device__ float g_kall [L_LAYERS * MS_SLOTS * C_DIM];
__device__ float g_vall [L_LAYERS * MS_SLOTS * C_DIM];
__device__ float g_Ptall[L_LAYERS * MS_SLOTS * C_DIM];
__device__ float g_pool[C_DIM];
__device__ int   g_cnt   [N_NODES];
__device__ int   g_rowptr[N_NODES + 1];
__device__ int   g_cursor[N_NODES];
__device__ int   g_csrc  [N_EDGES];

// ---------------- Wtg = Wt @ Wg (fp32, small) ----------------------------------
__global__ void wtg_kernel(const float* __restrict__ Wt, const float* __restrict__ Wg,
                           float* __restrict__ Wtg) {
    __shared__ float swt[8][C_DIM];
    int l = blockIdx.x >> 3;
    int t0 = (blockIdx.x & 7) * 8;
    int c = threadIdx.x;
    const float* wt = Wt + (size_t)l * T_DIM * C_DIM;
    const float* wg = Wg + (size_t)l * C_DIM * C_DIM;
    for (int i = threadIdx.x; i < 8 * C_DIM; i += blockDim.x)
        (&swt[0][0])[i] = wt[(t0 + i / C_DIM) * C_DIM + (i % C_DIM)];
    __syncthreads();
    float acc[8];
#pragma unroll
    for (int j = 0; j < 8; j++) acc[j] = 0.f;
    for (int c2 = 0; c2 < C_DIM; c2++) {
        float wv = wg[c2 * C_DIM + c];
#pragma unroll
        for (int j = 0; j < 8; j++) acc[j] += swt[j][c2] * wv;
    }
#pragma unroll
    for (int j = 0; j < 8; j++)
        Wtg[(size_t)l * T_DIM * C_DIM + (t0 + j) * C_DIM + c] = acc[j];
}

// ---------------- fused prep (also zeroes pool) --------------------------------
#define CPX (N_NODES * 128)
#define CPT (N_NODES * T_DIM)
#define CWI (64 * C_DIM)
#define CWC (L_LAYERS * (KCAT / 2) * C_DIM)
#define PREP_TOTAL (CPX + CPT + CWI + CWC + C_DIM)

__device__ __forceinline__ uint32_t pack_h2(float w0, float w1) {
    __half2 p = __floats2half2_rn(w0, w1);
    return *reinterpret_cast<uint32_t*>(&p);
}

__global__ void prep_kernel(const float* __restrict__ x, const float* __restrict__ te,
                            const float* __restrict__ Wi, const float* __restrict__ Wg,
                            const float* __restrict__ Wtg,
                            __half* __restrict__ xbf,
                            __half* __restrict__ cat0, __half* __restrict__ cat1,
                            uint32_t* __restrict__ wipk, uint32_t* __restrict__ wcpk,
                            float* __restrict__ pool) {
    int i = blockIdx.x * blockDim.x + threadIdx.x;
    if (i < CPX) { xbf[i] = __float2half_rn(x[i]); return; }
    i -= CPX;
    if (i < CPT) {
        int n = i / T_DIM, t = i % T_DIM;
        __half v = __float2half_rn(te[i]);
        cat0[(size_t)n * CAT_LD + C_DIM + t] = v;
        cat1[(size_t)n * CAT_LD + C_DIM + t] = v;
        return;
    }
    i -= CPT;
    if (i < CWI) {
        int n = i % C_DIM, k2 = i / C_DIM;
        wipk[i] = pack_h2(Wi[(2 * k2) * C_DIM + n], Wi[(2 * k2 + 1) * C_DIM + n]);
        return;
    }
    i -= CWI;
    if (i < CWC) {
        int r = i % ((KCAT / 2) * C_DIM);
        int l = i / ((KCAT / 2) * C_DIM);
        int n = r % C_DIM, k2 = r / C_DIM;
        int k = 2 * k2;
        float w0, w1;
        if (k < C_DIM) {
            const float* w = Wg + (size_t)l * C_DIM * C_DIM;
            w0 = w[k * C_DIM + n];
            w1 = w[(k + 1) * C_DIM + n];
        } else {
            const float* w = Wtg + (size_t)l * T_DIM * C_DIM;
            w0 = w[(k - C_DIM) * C_DIM + n];
            w1 = w[(k + 1 - C_DIM) * C_DIM + n];
        }
        wcpk[i] = pack_h2(w0, w1);
        return;
    }
    i -= CWC;
    if (i < C_DIM) pool[i] = 0.f;
}

// ---------------- CSR build ---------------------------------------------------
__global__ void zero_int_kernel(int* p, int n) {
    int i = blockIdx.x * blockDim.x + threadIdx.x;
    if (i < n) p[i] = 0;
}
__global__ void count_kernel(const int* __restrict__ dst, int* __restrict__ cnt) {
    int e = blockIdx.x * blockDim.x + threadIdx.x;
    if (e < N_EDGES) atomicAdd(&cnt[dst[e]], 1);
}

__global__ void scan_kernel(const int* __restrict__ cnt,
                            int* __restrict__ rowptr, int* __restrict__ cursor) {
    const int PER = (N_NODES + 1023) / 1024;
    int tid = threadIdx.x;
    int s0 = tid * PER;
    int vals[PER];
    int local = 0;
#pragma unroll
    for (int k = 0; k < PER; k++) {
        int i = s0 + k;
        vals[k] = (i < N_NODES) ? cnt[i] : 0;
        local += vals[k];
    }
    int lane = tid & 31, w = tid >> 5;
    int x = local;
#pragma unroll
    for (int off = 1; off < 32; off <<= 1) {
        int t = __shfl_up_sync(0xFFFFFFFFu, x, off);
        if (lane >= off) x += t;
    }
    __shared__ int wsum[32];
    if (lane == 31) wsum[w] = x;
    __syncthreads();
    if (w == 0) {
        int y = wsum[lane];
#pragma unroll
        for (int off = 1; off < 32; off <<= 1) {
            int t = __shfl_up_sync(0xFFFFFFFFu, y, off);
            if (lane >= off) y += t;
        }
        wsum[lane] = y;
    }
    __syncthreads();
    int warpoff = (w > 0) ? wsum[w - 1] : 0;
    int excl = warpoff + x - local;
#pragma unroll
    for (int k = 0; k < PER; k++) {
        int i = s0 + k;
        if (i < N_NODES) { rowptr[i] = excl; cursor[i] = excl; }
        excl += vals[k];
    }
    if (tid == 1023) rowptr[N_NODES] = warpoff + x;
}

__global__ void scatter_kernel(const int* __restrict__ src, const int* __restrict__ dst,
                               int* __restrict__ cursor, int* __restrict__ csrc) {
    int e = blockIdx.x * blockDim.x + threadIdx.x;
    if (e < N_EDGES) {
        int pos = atomicAdd(&cursor[dst[e]], 1);
        csrc[pos] = src[e];
    }
}

// ---------------- k/v/Pt for all layers (two pipelined launches) ----------------
__global__ void kvall_kernel(const float* __restrict__ mem, const float* __restrict__ Wk,
                             const float* __restrict__ Wv,
                             float* __restrict__ kall, float* __restrict__ vall) {
    __shared__ float sm[MD_DIM];
    int l = blockIdx.x / MS_SLOTS;
    int m = blockIdx.x % MS_SLOTS;
    int c = threadIdx.x;
    for (int i = threadIdx.x; i < MD_DIM; i += blockDim.x) sm[i] = mem[m * MD_DIM + i];
    __syncthreads();
    const float* wk = Wk + (size_t)l * MD_DIM * C_DIM;
    const float* wv = Wv + (size_t)l * MD_DIM * C_DIM;
    float ak = 0.f, av = 0.f;
#pragma unroll 4
    for (int t = 0; t < MD_DIM; t++) {
        float mv = sm[t];
        ak += mv * wk[t * C_DIM + c];
        av += mv * wv[t * C_DIM + c];
    }
    kall[(size_t)blockIdx.x * C_DIM + c] = ak;
    vall[(size_t)blockIdx.x * C_DIM + c] = av;
}

__global__ void ptall_kernel(const float* __restrict__ Wq, const float* __restrict__ kall,
                             float* __restrict__ Ptall) {
    __shared__ float sk[C_DIM];
    int l = blockIdx.x / MS_SLOTS;
    int c = threadIdx.x;
    for (int i = threadIdx.x; i < C_DIM; i += blockDim.x)
        sk[i] = kall[(size_t)blockIdx.x * C_DIM + i];
    __syncthreads();
    const float* wq = Wq + (size_t)l * C_DIM * C_DIM + (size_t)c * C_DIM;
    float acc = 0.f;
#pragma unroll 4
    for (int c2 = 0; c2 < C_DIM; c2++) acc += wq[c2] * sk[c2];
    Ptall[(size_t)blockIdx.x * C_DIM + c] = acc;
}

// ---------------- FP16 tensor-core GEMM (m16n8k16), cp.async 3-stage ----------
#define TBM 160
#define TBN 128
#define TBK 32
#define NSTAGE 3
#define AS32 ((TBK / 2) + 4)
#define A_ST (TBM * AS32)
#define B_ST ((TBK / 2) * 136)
#define SMEM_U32 (NSTAGE * (A_ST + B_ST))

__device__ __forceinline__ void mma_f16(float* c, const uint32_t* a,
                                        uint32_t b0, uint32_t b1) {
    asm volatile(
        "mma.sync.aligned.m16n8k16.row.col.f32.f16.f16.f32 "
        "{%0,%1,%2,%3}, {%4,%5,%6,%7}, {%8,%9}, {%0,%1,%2,%3};\n"
        : "+f"(c[0]), "+f"(c[1]), "+f"(c[2]), "+f"(c[3])
        : "r"(a[0]), "r"(a[1]), "r"(a[2]), "r"(a[3]), "r"(b0), "r"(b1));
}

__device__ __forceinline__ void cp_async16(void* dst_smem, const void* src) {
    uint32_t d = (uint32_t)__cvta_generic_to_shared(dst_smem);
    asm volatile("cp.async.cg.shared.global [%0], [%1], 16;\n" :: "r"(d), "l"(src));
}
__device__ __forceinline__ void cp_commit() {
    asm volatile("cp.async.commit_group;\n");
}
template <int NN>
__device__ __forceinline__ void cp_wait() {
    asm volatile("cp.async.wait_group %0;\n" :: "n"(NN));
}

__global__ __launch_bounds__(256, 2)
void hgemm_kernel(const __half* __restrict__ A, int lda,
                  const uint32_t* __restrict__ Bpk,
                  const float* __restrict__ bias,
                  const float* __restrict__ Asv, const float* __restrict__ Adv,
                  float* __restrict__ es, float* __restrict__ ed,
                  __half* __restrict__ Cout, int out_ld,
                  int M, int Nn, int K, int epi) {
    extern __shared__ uint32_t smem[];
    uint32_t* As = smem;
    uint32_t* Bs = smem + NSTAGE * A_ST;

    int tid = threadIdx.x;
    int lane = tid & 31;
    int wid = tid >> 5;
    int wm = wid >> 2;
    int wn = wid & 3;
    int tg = lane & 3;
    int gid = lane >> 2;

    int bm = blockIdx.y * TBM;
    int bn = blockIdx.x * TBN;
    int nk = K / TBK;

    int b_r = tid >> 4;
    int b_c = (tid & 15) * 8;
    const __half* a_src_base = A + (size_t)(bm + tid) * lda;
    const uint32_t* b_src = Bpk + (size_t)b_r * Nn + bn + b_c;

#pragma unroll
    for (int s = 0; s < NSTAGE - 1; s++) {
        if (s < nk) {
            int k0 = s * TBK;
            if (tid < TBM) {
                uint32_t* ad = As + s * A_ST + tid * AS32;
                const __half* asrc = a_src_base + k0;
#pragma unroll
                for (int j = 0; j < 4; j++) cp_async16(ad + j * 4, asrc + j * 8);
            }
            uint32_t* bd = Bs + s * B_ST + b_r * 136 + b_c;
            size_t soff = (size_t)(k0 / 2) * Nn;
            cp_async16(bd, b_src + soff);
            cp_async16(bd + 4, b_src + soff + 4);
        }
        cp_commit();
    }

    float acc[5][4][4];
#pragma unroll
    for (int mt = 0; mt < 5; mt++)
#pragma unroll
        for (int nt = 0; nt < 4; nt++)
#pragma unroll
            for (int r = 0; r < 4; r++) acc[mt][nt][r] = 0.f;

    for (int kt = 0; kt < nk; kt++) {
        cp_wait<NSTAGE - 2>();
        __syncthreads();

        const uint32_t* as_ = As + (kt % NSTAGE) * A_ST;
        const uint32_t* bs_ = Bs + (kt % NSTAGE) * B_ST;

#pragma unroll
        for (int s = 0; s < 2; s++) {
            int k2q = s * 8;
            uint32_t af[5][4];
#pragma unroll
            for (int mt = 0; mt < 5; mt++) {
                int m0 = wm * 80 + mt * 16 + gid;
                af[mt][0] = as_[m0 * AS32 + k2q + tg];
                af[mt][1] = as_[(m0 + 8) * AS32 + k2q + tg];
                af[mt][2] = as_[m0 * AS32 + k2q + tg + 4];
                af[mt][3] = as_[(m0 + 8) * AS32 + k2q + tg + 4];
            }
#pragma unroll
            for (int nt = 0; nt < 4; nt++) {
                int n0 = wn * 32 + nt * 8 + gid;
                uint32_t b0 = bs_[(k2q + tg) * 136 + n0];
                uint32_t b1 = bs_[(k2q + tg + 4) * 136 + n0];
#pragma unroll
                for (int mt = 0; mt < 5; mt++)
                    mma_f16(acc[mt][nt], af[mt], b0, b1);
            }
        }

        int s2 = (kt + NSTAGE - 1) % NSTAGE;
        if (kt + NSTAGE - 1 < nk) {
            int k0 = (kt + NSTAGE - 1) * TBK;
            if (tid < TBM) {
                uint32_t* ad = As + s2 * A_ST + tid * AS32;
                const __half* asrc = a_src_base + k0;
#pragma unroll
                for (int j = 0; j < 4; j++) cp_async16(ad + j * 4, asrc + j * 8);
            }
            uint32_t* bd = Bs + s2 * B_ST + b_r * 136 + b_c;
            size_t soff = (size_t)(k0 / 2) * Nn;
            cp_async16(bd, b_src + soff);
            cp_async16(bd + 4, b_src + soff + 4);
        }
        cp_commit();
    }

    // ---- epilogue ----
    float as_c[8], ad_c[8];
    if (epi == 3) {
#pragma unroll
        for (int nt = 0; nt < 4; nt++) {
            int c = bn + wn * 32 + nt * 8 + tg * 2;
            as_c[nt * 2]     = Asv[c];
            as_c[nt * 2 + 1] = Asv[c + 1];
            ad_c[nt * 2]     = Adv[c];
            ad_c[nt * 2 + 1] = Adv[c + 1];
        }
    }
    int head = (bn >> 5) + wn;

#pragma unroll
    for (int mt = 0; mt < 5; mt++) {
#pragma unroll
        for (int half = 0; half < 2; half++) {
            int r = bm + wm * 80 + mt * 16 + gid + half * 8;
            float ps = 0.f, pd = 0.f;
#pragma unroll
            for (int nt = 0; nt < 4; nt++) {
                int c = bn + wn * 32 + nt * 8 + tg * 2;
                float v0 = acc[mt][nt][half * 2 + 0];
                float v1 = acc[mt][nt][half * 2 + 1];
                if (epi == 1) {
                    v0 = fmaxf(v0 + bias[c], 0.f);
                    v1 = fmaxf(v1 + bias[c + 1], 0.f);
                } else {
                    ps += v0 * as_c[nt * 2] + v1 * as_c[nt * 2 + 1];
                    pd += v0 * ad_c[nt * 2] + v1 * ad_c[nt * 2 + 1];
                }
                __half2 pv = __floats2half2_rn(v0, v1);
                *reinterpret_cast<__half2*>(&Cout[(size_t)r * out_ld + c]) = pv;
            }
            if (epi == 3) {
                ps += __shfl_xor_sync(0xFFFFFFFFu, ps, 1);
                ps += __shfl_xor_sync(0xFFFFFFFFu, ps, 2);
                pd += __shfl_xor_sync(0xFFFFFFFFu, pd, 1);
                pd += __shfl_xor_sync(0xFFFFFFFFu, pd, 2);
                if (tg == 0) {
                    es[r * H_HEADS + head] = ps;
                    ed[r * H_HEADS + head] = pd;
                }
            }
        }
    }
}

// ---------------- fused edge aggregation + memory cross-attention --------------
// node_out written fp16 into cols 0..255 of the next cat buffer (stride CAT_LD).
// If pool_out != null (last layer), block-accumulate node outputs into pool.
__global__ __launch_bounds__(256)
void edge_mem_kernel(const __half* __restrict__ h, const int* __restrict__ rowptr,
                     const int* __restrict__ csrc, const float* __restrict__ es,
                     const float* __restrict__ ed,
                     const float* __restrict__ Pt, const float* __restrict__ vb,
                     const __half* __restrict__ xin,
                     __half* __restrict__ node_out, float* __restrict__ pool_out) {
    __shared__ float sp[MS_SLOTS][C_DIM];
    __shared__ float sv[MS_SLOTS][C_DIM];
    __shared__ float sw[8][32][8];
    __shared__ int   ss[8][32];
    __shared__ float spool[C_DIM];
    for (int i = threadIdx.x; i < MS_SLOTS * C_DIM; i += blockDim.x) {
        (&sp[0][0])[i] = Pt[i];
        (&sv[0][0])[i] = vb[i];
    }
    if (pool_out) spool[threadIdx.x] = 0.f;
    __syncthreads();

    int warp = threadIdx.x >> 5, lane = threadIdx.x & 31;
    int n = blockIdx.x * 8 + warp;   // grid*8 == N_NODES exactly; no early return
    int beg = rowptr[n], end = rowptr[n + 1];

    float edn[8];
#pragma unroll
    for (int j = 0; j < 8; j++) edn[j] = ed[n * 8 + j];

    int head = lane >> 2;
    float acc[8];
#pragma unroll
    for (int k = 0; k < 8; k++) acc[k] = 0.f;
    float dsum[8];
#pragma unroll
    for (int j = 0; j < 8; j++) dsum[j] = 0.f;

    for (int base = beg; base < end; base += 32) {
        int i = base + lane;
        int s = -1;
        float w[8];
        if (i < end) {
            s = csrc[i];
#pragma unroll
            for (int j = 0; j < 8; j++) {
                float lg = es[s * 8 + j] + edn[j];
                lg = (lg > 0.f) ? lg : NEG_SLOPE * lg;
                w[j] = __expf(lg);
                dsum[j] += w[j];
            }
        } else {
#pragma unroll
            for (int j = 0; j < 8; j++) w[j] = 0.f;
        }
        ss[warp][lane] = s;
#pragma unroll
        for (int j = 0; j < 8; j++) sw[warp][lane][j] = w[j];
        __syncwarp();
        int cnt = min(32, end - base);
        if (cnt > 0) {
            uint4 pf[4];
#pragma unroll
            for (int k = 0; k < 4; k++) {
                if (k < cnt)
                    pf[k] = *reinterpret_cast<const uint4*>(
                        &h[(size_t)ss[warp][k] * C_DIM + lane * 8]);
            }
            for (int e2 = 0; e2 < cnt; e2++) {
                uint4 cur = pf[e2 & 3];
                int nxt = e2 + 4;
                if (nxt < cnt) {
                    pf[e2 & 3] = *reinterpret_cast<const uint4*>(
                        &h[(size_t)ss[warp][nxt] * C_DIM + lane * 8]);
                }
                float we = sw[warp][e2][head];
                float2 f0 = __half22float2(*reinterpret_cast<__half2*>(&cur.x));
                float2 f1 = __half22float2(*reinterpret_cast<__half2*>(&cur.y));
                float2 f2 = __half22float2(*reinterpret_cast<__half2*>(&cur.z));
                float2 f3 = __half22float2(*reinterpret_cast<__half2*>(&cur.w));
                acc[0] += we * f0.x; acc[1] += we * f0.y;
                acc[2] += we * f1.x; acc[3] += we * f1.y;
                acc[4] += we * f2.x; acc[5] += we * f2.y;
                acc[6] += we * f3.x; acc[7] += we * f3.y;
            }
        }
        __syncwarp();
    }
#pragma unroll
    for (int off = 16; off > 0; off >>= 1)
#pragma unroll
        for (int j = 0; j < 8; j++) dsum[j] += __shfl_xor_sync(0xFFFFFFFFu, dsum[j], off);

    float inv = 1.0f / (dsum[head] + 1e-16f);
    float mid[8];
#pragma unroll
    for (int j = 0; j < 8; j++) mid[j] = fmaxf(acc[j] * inv, 0.f);

    float s[MS_SLOTS];
#pragma unroll
    for (int m = 0; m < MS_SLOTS; m++) {
        const float* pr = &sp[m][lane * 8];
        float p = mid[0] * pr[0] + mid[1] * pr[1] + mid[2] * pr[2] + mid[3] * pr[3]
                + mid[4] * pr[4] + mid[5] * pr[5] + mid[6] * pr[6] + mid[7] * pr[7];
#pragma unroll
        for (int off = 16; off > 0; off >>= 1) p += __shfl_xor_sync(0xFFFFFFFFu, p, off);
        s[m] = p * 0.0625f;
    }
    float mx = s[0];
#pragma unroll
    for (int m = 1; m < MS_SLOTS; m++) mx = fmaxf(mx, s[m]);
    float sum = 0.f;
#pragma unroll
    for (int m = 0; m < MS_SLOTS; m++) { s[m] = __expf(s[m] - mx); sum += s[m]; }
    float invs = 1.0f / sum;

    uint4 xv = *reinterpret_cast<const uint4*>(&xin[(size_t)n * CAT_LD + lane * 8]);
    float2 x0 = __half22float2(*reinterpret_cast<__half2*>(&xv.x));
    float2 x1 = __half22float2(*reinterpret_cast<__half2*>(&xv.y));
    float2 x2 = __half22float2(*reinterpret_cast<__half2*>(&xv.z));
    float2 x3 = __half22float2(*reinterpret_cast<__half2*>(&xv.w));
    float o[8] = {mid[0] + x0.x, mid[1] + x0.y, mid[2] + x1.x, mid[3] + x1.y,
                  mid[4] + x2.x, mid[5] + x2.y, mid[6] + x3.x, mid[7] + x3.y};
#pragma unroll
    for (int m = 0; m < MS_SLOTS; m++) {
        float a = s[m] * invs;
        const float4* vp = reinterpret_cast<const float4*>(&sv[m][lane * 8]);
        float4 v0 = vp[0], v1 = vp[1];
        o[0] += a * v0.x; o[1] += a * v0.y; o[2] += a * v0.z; o[3] += a * v0.w;
        o[4] += a * v1.x; o[5] += a * v1.y; o[6] += a * v1.z; o[7] += a * v1.w;
    }
#pragma unroll
    for (int j = 0; j < 8; j++) o[j] = fmaxf(o[j], 0.f);
    __half2 b0 = __floats2half2_rn(o[0], o[1]);
    __half2 b1 = __floats2half2_rn(o[2], o[3]);
    __half2 b2 = __floats2half2_rn(o[4], o[5]);
    __half2 b3 = __floats2half2_rn(o[6], o[7]);
    uint4 pk;
    pk.x = *reinterpret_cast<uint32_t*>(&b0);
    pk.y = *reinterpret_cast<uint32_t*>(&b1);
    pk.z = *reinterpret_cast<uint32_t*>(&b2);
    pk.w = *reinterpret_cast<uint32_t*>(&b3);
    *reinterpret_cast<uint4*>(&node_out[(size_t)n * CAT_LD + lane * 8]) = pk;

    if (pool_out) {
#pragma unroll
        for (int j = 0; j < 8; j++) atomicAdd(&spool[lane * 8 + j], o[j]);
        __syncthreads();
        atomicAdd(&pool_out[threadIdx.x], spool[threadIdx.x]);
    }
}

// ---------------- final projection ---------------------------------------------
__global__ void final_kernel(const float* __restrict__ pool, const float* __restrict__ mem,
                             const float* __restrict__ Wc, const float* __restrict__ bc,
                             float* __restrict__ out) {
    __shared__ float s0[512], s1[512];
    int i = threadIdx.x;
    float val = 0.f;
    if (i < C_DIM) {
        val = pool[i] * (1.0f / (float)N_NODES);
    } else if (i < C_DIM + MD_DIM) {
        int t = i - C_DIM;
        float a = 0.f;
#pragma unroll
        for (int m = 0; m < MS_SLOTS; m++) a += mem[m * MD_DIM + t];
        val = a * (1.0f / (float)MS_SLOTS);
    }
    float c0 = 0.f, c1 = 0.f;
    if (i < C_DIM + MD_DIM) { c0 = val * Wc[i * 2 + 0]; c1 = val * Wc[i * 2 + 1]; }
    s0[i] = c0; s1[i] = c1;
    __syncthreads();
    for (int st = 256; st > 0; st >>= 1) {
        if (i < st) { s0[i] += s0[i + st]; s1[i] += s1[i + st]; }
        __syncthreads();
    }
    if (i == 0) { out[0] = s0[0] + bc[0]; out[1] = s1[0] + bc[1]; }
}

// ---------------- streams -----------------------------------------------------
struct StreamBundle {
    cudaStream_t s1 = nullptr, s2 = nullptr;
    cudaEvent_t evFork = nullptr, evS1 = nullptr, evS2 = nullptr;
    bool ok = false;
    StreamBundle() {
        ok = (cudaStreamCreateWithFlags(&s1, cudaStreamNonBlocking) == cudaSuccess) &&
             (cudaStreamCreateWithFlags(&s2, cudaStreamNonBlocking) == cudaSuccess) &&
             (cudaEventCreateWithFlags(&evFork, cudaEventDisableTiming) == cudaSuccess) &&
             (cudaEventCreateWithFlags(&evS1, cudaEventDisableTiming) == cudaSuccess) &&
             (cudaEventCreateWithFlags(&evS2, cudaEventDisableTiming) == cudaSuccess);
    }
};
static StreamBundle g_sb;

// ---------------- host launch -------------------------------------------------
static void* getsym(const void* symbol) {
    void* p = nullptr;
    cudaGetSymbolAddress(&p, symbol);
    return p;
}

extern "C" void kernel_launch(void* const* d_in, const int* in_sizes, int n_in,
                              void* d_out, int out_size) {
    const float* x    = (const float*)d_in[0];
    const int*   ei   = (const int*)  d_in[1];
    const float* te   = (const float*)d_in[2];
    const float* Wi   = (const float*)d_in[3];
    const float* bi   = (const float*)d_in[4];
    const float* Wg   = (const float*)d_in[5];
    const float* a_s  = (const float*)d_in[6];
    const float* a_d  = (const float*)d_in[7];
    const float* Wt   = (const float*)d_in[8];
    const float* Wq   = (const float*)d_in[9];
    const float* Wk   = (const float*)d_in[10];
    const float* Wv   = (const float*)d_in[11];
    const float* mem  = (const float*)d_in[12];
    const float* Wc   = (const float*)d_in[13];
    const float* bc   = (const float*)d_in[14];
    float* out = (float*)d_out;

    __half* cat0 = (__half*)getsym(g_cat0);
    __half* cat1 = (__half*)getsym(g_cat1);
    __half* hbf  = (__half*)getsym(g_hbf);
    __half* xbf  = (__half*)getsym(g_xbf);
    float* Wtg  = (float*)getsym(g_Wtg);
    uint32_t* Wipk = (uint32_t*)getsym(g_Wipk);
    uint32_t* Wcpk = (uint32_t*)getsym(g_Wcpk);
    float* esb   = (float*)getsym(g_es);
    float* edb   = (float*)getsym(g_ed);
    float* kall  = (float*)getsym(g_kall);
    float* vall  = (float*)getsym(g_vall);
    float* Ptall = (float*)getsym(g_Ptall);
    float* pool  = (float*)getsym(g_pool);
    int* cnt     = (int*)getsym(g_cnt);
    int* rowptr  = (int*)getsym(g_rowptr);
    int* cursor  = (int*)getsym(g_cursor);
    int* csrc    = (int*)getsym(g_csrc);

    const int* src = ei;
    const int* dst = ei + N_EDGES;

    const int smem_bytes = SMEM_U32 * 4;   // 64512
    static bool attr_set = false;
    if (!attr_set) {
        cudaFuncSetAttribute(hgemm_kernel, cudaFuncAttributeMaxDynamicSharedMemorySize,
                             smem_bytes);
        attr_set = true;
    }

    bool use_streams = g_sb.ok;
    cudaStream_t sc = use_streams ? g_sb.s1 : (cudaStream_t)0;
    cudaStream_t sk = use_streams ? g_sb.s2 : (cudaStream_t)0;

    if (use_streams) {
        cudaEventRecord(g_sb.evFork, 0);
        cudaStreamWaitEvent(g_sb.s1, g_sb.evFork, 0);
        cudaStreamWaitEvent(g_sb.s2, g_sb.evFork, 0);
    }

    // side stream 1: CSR build (hidden under main-stream prep + GEMMs)
    zero_int_kernel<<<(N_NODES + 255) / 256, 256, 0, sc>>>(cnt, N_NODES);
    count_kernel<<<(N_EDGES + 255) / 256, 256, 0, sc>>>(dst, cnt);
    scan_kernel<<<1, 1024, 0, sc>>>(cnt, rowptr, cursor);
    scatter_kernel<<<(N_EDGES + 255) / 256, 256, 0, sc>>>(src, dst, cursor, csrc);

    // side stream 2: k/v then Pt (two pipelined launches)
    kvall_kernel<<<L_LAYERS * MS_SLOTS, 256, 0, sk>>>(mem, Wk, Wv, kall, vall);
    ptall_kernel<<<L_LAYERS * MS_SLOTS, 256, 0, sk>>>(Wq, kall, Ptall);

    if (use_streams) {
        cudaEventRecord(g_sb.evS1, g_sb.s1);
        cudaEventRecord(g_sb.evS2, g_sb.s2);
    }

    // main stream: Wtg = Wt@Wg, then converts + packing (+pool zero)
    wtg_kernel<<<L_LAYERS * 8, 256>>>(Wt, Wg, Wtg);
    prep_kernel<<<(PREP_TOTAL + 255) / 256, 256>>>(x, te, Wi, Wg, Wtg, xbf, cat0, cat1,
                                                   Wipk, Wcpk, pool);

    // input projection: cat0[:,0:256] = relu(x @ Wi + bi)   (fp16, stride 320)
    dim3 gemm_grid(C_DIM / TBN, N_NODES / TBM);   // (2, 125)
    hgemm_kernel<<<gemm_grid, 256, smem_bytes>>>(xbf, 128, Wipk, bi,
                                                 nullptr, nullptr, nullptr, nullptr,
                                                 cat0, CAT_LD, N_NODES, C_DIM, 128, 1);

    if (use_streams) {
        cudaStreamWaitEvent(0, g_sb.evS1, 0);
        cudaStreamWaitEvent(0, g_sb.evS2, 0);
    }

    __half* cur = cat0;
    __half* nxt = cat1;
    for (int l = 0; l < L_LAYERS; l++) {
        hgemm_kernel<<<gemm_grid, 256, smem_bytes>>>(cur, CAT_LD,
                                                     Wcpk + (size_t)l * (KCAT / 2) * C_DIM,
                                                     nullptr,
                                                     a_s + l * H_HEADS * D_HEAD,
                                                     a_d + l * H_HEADS * D_HEAD, esb, edb,
                                                     hbf, C_DIM, N_NODES, C_DIM, KCAT, 3);
        float* pout = (l == L_LAYERS - 1) ? pool : nullptr;
        edge_mem_kernel<<<N_NODES / 8, 256>>>(hbf, rowptr, csrc, esb, edb,
                                              Ptall + (size_t)l * MS_SLOTS * C_DIM,
                                              vall + (size_t)l * MS_SLOTS * C_DIM,
                                              cur, nxt, pout);
        __half* tmp = cur; cur = nxt; nxt = tmp;
    }

    final_kernel<<<1, 512>>>(pool, mem, Wc, bc, out);
}